// round 6
// baseline (speedup 1.0000x reference)
#include <cuda_runtime.h>
#include <cstdint>

// Problem constants (fixed by the reference)
#define HW_TOTAL (512 * 512)                  // 262144 pixels per batch image
#define BATCH 32
#define PSAMP 8192
#define NSAMP (BATCH * PSAMP)                 // 262144 samples
#define CHUNK 2048                            // pixels per logical chunk
#define CPB 128                               // chunks per batch
#define NCHUNKS (BATCH * CPB)                 // 4096
#define GPB 1024                              // 256-px groups per batch
#define EPS_F 1e-5f

#define CNT_BLOCKS (NCHUNKS / 2)              // 2048 (2 chunks per block)
#define SMP_BLOCKS (NSAMP / 512)              // 512
#define SMP_PER_BATCH (SMP_BLOCKS / BATCH)    // 16 blocks per batch

// -------- device scratch (static globals: no runtime allocation) --------
__device__ __align__(256) unsigned char g_bytes[(size_t)NCHUNKS * 256]; // 1 MB packed mask
__device__ __align__(16)  unsigned short g_subOff[NCHUNKS * 8];         // 64 KB group offsets in chunk
__device__ int      g_chunkCnt[NCHUNKS];
__device__ int      g_chunkOff[NCHUNKS];      // exclusive offsets within batch
__device__ int      g_validNum[BATCH];
__device__ double   g_sum1, g_sum2;
__device__ int      g_cnt1, g_cnt2;
__device__ unsigned g_done1, g_done2;         // zero-init; self-resetting

// ======== kernel 1: mask -> bitmask + subOff + chunk counts; last block scans
__global__ void __launch_bounds__(512) k_count(const int* __restrict__ mask) {
    const int t = threadIdx.x, lane = t & 31, wid = t >> 5;
    const int half = (t >= 256);                   // which chunk of the pair
    const int chunk = blockIdx.x * 2 + half;
    const int tc = t & 255;                        // thread index within chunk

    // ---- read 8 mask ints, build packed byte ----
    const int4* p = reinterpret_cast<const int4*>(mask + (size_t)chunk * CHUNK);
    int4 a = p[tc * 2];
    int4 b = p[tc * 2 + 1];
    unsigned byte = (unsigned)(a.x != 0)      | (unsigned)(a.y != 0) << 1
                  | (unsigned)(a.z != 0) << 2 | (unsigned)(a.w != 0) << 3
                  | (unsigned)(b.x != 0) << 4 | (unsigned)(b.y != 0) << 5
                  | (unsigned)(b.z != 0) << 6 | (unsigned)(b.w != 0) << 7;
    g_bytes[(size_t)chunk * 256 + tc] = (unsigned char)byte;

    // ---- warp (=256-px group) popcount sums ----
    int c = __popc(byte);
    #pragma unroll
    for (int o = 16; o; o >>= 1) c += __shfl_down_sync(0xFFFFFFFFu, c, o);

    __shared__ int ws[16];
    if (lane == 0) ws[wid] = c;
    __syncthreads();

    if (tc == 0) {    // t==0 (chunk A) and t==256 (chunk B)
        __align__(16) unsigned short so[8];
        int e = 0;
        #pragma unroll
        for (int g = 0; g < 8; g++) { so[g] = (unsigned short)e; e += ws[half * 8 + g]; }
        *reinterpret_cast<uint4*>(&g_subOff[chunk * 8]) =
            *reinterpret_cast<const uint4*>(so);
        g_chunkCnt[chunk] = e;
    }

    // ---- last-block-done: per-batch scan of chunk counts + zero accumulators
    __shared__ int isLast;
    __threadfence();
    if (t == 0) isLast = (atomicAdd(&g_done1, 1) == CNT_BLOCKS - 1);
    __syncthreads();
    if (!isLast) return;

    if (t == 0) {
        g_done1 = 0;                          // reset for next graph replay
        g_sum1 = 0.0; g_sum2 = 0.0; g_cnt1 = 0; g_cnt2 = 0;
    }
    // 16 warps; warp w scans batches w and w+16 (128 counts, 4/lane)
    for (int bb = wid; bb < BATCH; bb += 16) {
        int base = bb * CPB + lane * 4;
        int c0 = __ldcg(&g_chunkCnt[base + 0]);
        int c1 = __ldcg(&g_chunkCnt[base + 1]);
        int c2 = __ldcg(&g_chunkCnt[base + 2]);
        int c3 = __ldcg(&g_chunkCnt[base + 3]);
        int s4 = c0 + c1 + c2 + c3;
        int inc = s4;
        #pragma unroll
        for (int o = 1; o < 32; o <<= 1) {
            int v = __shfl_up_sync(0xFFFFFFFFu, inc, o);
            if (lane >= o) inc += v;
        }
        int exc = inc - s4;
        g_chunkOff[base + 0] = exc;
        g_chunkOff[base + 1] = exc + c0;
        g_chunkOff[base + 2] = exc + c0 + c1;
        g_chunkOff[base + 3] = exc + c0 + c1 + c2;
        int tot = __shfl_sync(0xFFFFFFFFu, inc, 31);
        if (lane == 0) g_validNum[bb] = tot;
    }
}

// ======== kernel 2: smem-resident select + gather + reduce; last block ends =
__global__ void __launch_bounds__(512) k_sample(const float* __restrict__ d3,
                                                const float* __restrict__ dp,
                                                const int* __restrict__ s1,
                                                const int* __restrict__ s2,
                                                float* __restrict__ out) {
    const int t = threadIdx.x, lane = t & 31, wid = t >> 5;
    const int b = blockIdx.x / SMP_PER_BATCH;            // batch of this block
    const int i = b * PSAMP + (blockIdx.x % SMP_PER_BATCH) * 512 + t;

    __shared__ ulonglong2      sbits[GPB * 2];           // 32 KB batch bitmask (2 per group)
    __shared__ int             sgoff[GPB + 1];           // 4 KB+4 group offsets
    __shared__ unsigned short  slut[GPB * 2];            // 4 KB rank(128) -> group
    __shared__ float sf1[16], sf2[16];
    __shared__ int   si1[16], si2[16];

    // ---- prologue: stage bitmask (32768 B = 2048 uint4) ----
    {
        const uint4* src = reinterpret_cast<const uint4*>(g_bytes + (size_t)b * 32768);
        uint4* dst = reinterpret_cast<uint4*>(sbits);
        #pragma unroll
        for (int k = 0; k < 4; k++) dst[t + 512 * k] = src[t + 512 * k];
    }
    // ---- prologue: group offsets = chunkOff + subOff (2 groups per thread) --
    #pragma unroll
    for (int k = 0; k < 2; k++) {
        int g = t * 2 + k;
        int ch = b * CPB + (g >> 3);
        sgoff[g] = g_chunkOff[ch] + (int)g_subOff[ch * 8 + (g & 7)];
    }
    if (t == 0) sgoff[GPB] = g_validNum[b];
    __syncthreads();

    // ---- prologue: build rank->group LUT (gran 128) ----
    #pragma unroll
    for (int kk = 0; kk < 2; kk++) {
        int g = t * 2 + kk;
        int start = sgoff[g], end = sgoff[g + 1];
        for (int k = (start + 127) >> 7; (k << 7) < end; k++)
            slut[k] = (unsigned short)g;
    }
    __syncthreads();

    const int vn = sgoff[GPB];
    const size_t bo = (size_t)b * HW_TOTAL;
    const int j1 = s1[i] % vn;
    const int j2 = s2[i] % vn;

    // ---- select both ranks (independent chains) ----
    int g1 = slut[j1 >> 7];
    int g2 = slut[j2 >> 7];
    while (sgoff[g1 + 1] <= j1) g1++;
    while (sgoff[g2 + 1] <= j2) g2++;
    int r1 = j1 - sgoff[g1];
    int r2 = j2 - sgoff[g2];
    ulonglong2 a0 = sbits[g1 * 2], a1 = sbits[g1 * 2 + 1];
    ulonglong2 b0 = sbits[g2 * 2], b1 = sbits[g2 * 2 + 1];

    int p1, p2;
    {
        unsigned long long w = a0.x; int wsel = 0;
        int q = __popcll(a0.x);
        if (r1 >= q) { r1 -= q; q = __popcll(a0.y);
            if (r1 >= q) { r1 -= q; q = __popcll(a1.x);
                if (r1 >= q) { r1 -= q; w = a1.y; wsel = 3; }
                else         {          w = a1.x; wsel = 2; } }
            else         {          w = a0.y; wsel = 1; } }
        unsigned lo = (unsigned)w; int pl = __popc(lo);
        int bit = (r1 < pl) ? (int)__fns(lo, 0, r1 + 1)
                            : 32 + (int)__fns((unsigned)(w >> 32), 0, r1 - pl + 1);
        p1 = g1 * 256 + wsel * 64 + bit;
    }
    {
        unsigned long long w = b0.x; int wsel = 0;
        int q = __popcll(b0.x);
        if (r2 >= q) { r2 -= q; q = __popcll(b0.y);
            if (r2 >= q) { r2 -= q; q = __popcll(b1.x);
                if (r2 >= q) { r2 -= q; w = b1.y; wsel = 3; }
                else         {          w = b1.x; wsel = 2; } }
            else         {          w = b0.y; wsel = 1; } }
        unsigned lo = (unsigned)w; int pl = __popc(lo);
        int bit = (r2 < pl) ? (int)__fns(lo, 0, r2 + 1)
                            : 32 + (int)__fns((unsigned)(w >> 32), 0, r2 - pl + 1);
        p2 = g2 * 256 + wsel * 64 + bit;
    }

    // ---- depth gathers + loss terms ----
    const float av = d3[bo + p1];
    const float bv = d3[bo + p2];
    const float diff = dp[bo + p1] - dp[bo + p2];

    float ls1 = 0.f, ls2 = 0.f;
    int lc1 = 0, lc2 = 0;
    if (av > bv + EPS_F) { ls1 = fmaxf(-diff, 0.f); lc1 = 1; }
    if (av < bv - EPS_F) { ls2 = fmaxf(diff, 0.f);  lc2 = 1; }

    #pragma unroll
    for (int o = 16; o; o >>= 1) {
        ls1 += __shfl_down_sync(0xFFFFFFFFu, ls1, o);
        ls2 += __shfl_down_sync(0xFFFFFFFFu, ls2, o);
        lc1 += __shfl_down_sync(0xFFFFFFFFu, lc1, o);
        lc2 += __shfl_down_sync(0xFFFFFFFFu, lc2, o);
    }
    if (lane == 0) { sf1[wid] = ls1; sf2[wid] = ls2; si1[wid] = lc1; si2[wid] = lc2; }
    __syncthreads();
    if (wid == 0) {
        float v1 = (lane < 16) ? sf1[lane] : 0.f;
        float v2 = (lane < 16) ? sf2[lane] : 0.f;
        int   i1 = (lane < 16) ? si1[lane] : 0;
        int   i2 = (lane < 16) ? si2[lane] : 0;
        #pragma unroll
        for (int o = 8; o; o >>= 1) {
            v1 += __shfl_down_sync(0xFFFFFFFFu, v1, o);
            v2 += __shfl_down_sync(0xFFFFFFFFu, v2, o);
            i1 += __shfl_down_sync(0xFFFFFFFFu, i1, o);
            i2 += __shfl_down_sync(0xFFFFFFFFu, i2, o);
        }
        if (lane == 0) {
            atomicAdd(&g_sum1, (double)v1);
            atomicAdd(&g_sum2, (double)v2);
            atomicAdd(&g_cnt1, i1);
            atomicAdd(&g_cnt2, i2);
        }
    }

    // ---- last-block finalize ----
    __threadfence();
    __syncthreads();
    if (t == 0) {
        if (atomicAdd(&g_done2, 1) == SMP_BLOCKS - 1) {
            g_done2 = 0;                       // reset for next graph replay
            double a1 = *(volatile double*)&g_sum1;
            double a2 = *(volatile double*)&g_sum2;
            int    n1 = *(volatile int*)&g_cnt1;
            int    n2 = *(volatile int*)&g_cnt2;
            out[0] = 0.5f * (float)(a1 / (double)n1 + a2 / (double)n2);
        }
    }
}

extern "C" void kernel_launch(void* const* d_in, const int* in_sizes, int n_in,
                              void* d_out, int out_size) {
    const float* d3   = (const float*)d_in[0];   // depth_3dmm
    const float* dp   = (const float*)d_in[1];   // depth_pigan
    const int*   mask = (const int*)d_in[2];
    const int*   s1   = (const int*)d_in[3];
    const int*   s2   = (const int*)d_in[4];

    k_count<<<CNT_BLOCKS, 512>>>(mask);
    k_sample<<<SMP_BLOCKS, 512>>>(d3, dp, s1, s2, (float*)d_out);
}

// round 8
// speedup vs baseline: 1.1430x; 1.1430x over previous
#include <cuda_runtime.h>
#include <cstdint>

// Problem constants (fixed by the reference)
#define HW_TOTAL (512 * 512)                  // 262144 pixels per batch image
#define BATCH 32
#define PSAMP 8192
#define NSAMP (BATCH * PSAMP)                 // 262144 samples
#define CHUNK 2048                            // pixels per logical chunk
#define CPB 128                               // chunks per batch
#define NCHUNKS (BATCH * CPB)                 // 4096
#define GPB 1024                              // 256-px groups per batch
#define LUTN 2048                             // rank->group LUT entries (gran 128)
#define EPS_F 1e-5f

#define CNT_BLOCKS (NCHUNKS / 2)              // 2048 (2 chunks per block)
#define SMP_BLOCKS (NSAMP / 512)              // 512 (512 samples per block)

// -------- device scratch (static globals: no runtime allocation) --------
__device__ __align__(256) unsigned char g_bytes[(size_t)NCHUNKS * 256]; // 1 MB packed mask
__device__ __align__(16)  unsigned short g_subOff[NCHUNKS * 8];         // 64 KB group offsets in chunk
__device__ int      g_chunkCnt[NCHUNKS];
__device__ __align__(16) int            g_grpOff[BATCH * GPB];          // 128 KB batch-rel group offsets
__device__ __align__(16) unsigned short g_lut[BATCH * LUTN];            // 128 KB rank(128)->group
__device__ int      g_validNum[BATCH];
__device__ double   g_sum1, g_sum2;
__device__ int      g_cnt1, g_cnt2;
__device__ unsigned g_done2;                  // zero-init; self-resetting

// ======== kernel 1: mask -> bitmask + subOff + chunk counts ========
__global__ void __launch_bounds__(512) k_count(const int* __restrict__ mask) {
    const int t = threadIdx.x, lane = t & 31, wid = t >> 5;
    const int half = (t >= 256);                   // which chunk of the pair
    const int chunk = blockIdx.x * 2 + half;
    const int tc = t & 255;                        // thread index within chunk

    const int4* p = reinterpret_cast<const int4*>(mask + (size_t)chunk * CHUNK);
    int4 a = p[tc * 2];
    int4 b = p[tc * 2 + 1];
    unsigned byte = (unsigned)(a.x != 0)      | (unsigned)(a.y != 0) << 1
                  | (unsigned)(a.z != 0) << 2 | (unsigned)(a.w != 0) << 3
                  | (unsigned)(b.x != 0) << 4 | (unsigned)(b.y != 0) << 5
                  | (unsigned)(b.z != 0) << 6 | (unsigned)(b.w != 0) << 7;
    g_bytes[(size_t)chunk * 256 + tc] = (unsigned char)byte;

    int c = __popc(byte);
    #pragma unroll
    for (int o = 16; o; o >>= 1) c += __shfl_down_sync(0xFFFFFFFFu, c, o);

    __shared__ int ws[16];
    if (lane == 0) ws[wid] = c;
    __syncthreads();

    if (tc == 0) {    // t==0 (chunk A) and t==256 (chunk B)
        __align__(16) unsigned short so[8];
        int e = 0;
        #pragma unroll
        for (int g = 0; g < 8; g++) { so[g] = (unsigned short)e; e += ws[half * 8 + g]; }
        *reinterpret_cast<uint4*>(&g_subOff[chunk * 8]) =
            *reinterpret_cast<const uint4*>(so);
        g_chunkCnt[chunk] = e;
    }
}

// ======== kernel 2: per-batch scan + grpOff + LUT precompute ========
// One block per batch, 256 threads.
__global__ void __launch_bounds__(256) k_prep() {
    const int b = blockIdx.x;
    const int t = threadIdx.x, lane = t & 31, wid = t >> 5;

    __shared__ int scoff[CPB];
    __shared__ int svn;

    if (wid == 0) {   // scan this batch's 128 chunk counts (4 per lane)
        int base = b * CPB + lane * 4;
        int c0 = g_chunkCnt[base + 0];
        int c1 = g_chunkCnt[base + 1];
        int c2 = g_chunkCnt[base + 2];
        int c3 = g_chunkCnt[base + 3];
        int s4 = c0 + c1 + c2 + c3;
        int inc = s4;
        #pragma unroll
        for (int o = 1; o < 32; o <<= 1) {
            int v = __shfl_up_sync(0xFFFFFFFFu, inc, o);
            if (lane >= o) inc += v;
        }
        int exc = inc - s4;
        scoff[lane * 4 + 0] = exc;
        scoff[lane * 4 + 1] = exc + c0;
        scoff[lane * 4 + 2] = exc + c0 + c1;
        scoff[lane * 4 + 3] = exc + c0 + c1 + c2;
        int tot = __shfl_sync(0xFFFFFFFFu, inc, 31);
        if (lane == 0) { g_validNum[b] = tot; svn = tot; }
    }
    __syncthreads();

    // group offsets = chunkOff + subOff (4 groups per thread)
    int* go = g_grpOff + b * GPB;
    #pragma unroll
    for (int k = 0; k < 4; k++) {
        int g = t * 4 + k;
        int ch = g >> 3;
        go[g] = scoff[ch] + (int)g_subOff[(b * CPB + ch) * 8 + (g & 7)];
    }
    __syncthreads();

    // rank(128) -> group LUT
    unsigned short* lut = g_lut + b * LUTN;
    const int vn = svn;
    #pragma unroll
    for (int k = 0; k < 4; k++) {
        int g = t * 4 + k;
        int start = go[g];
        int end = (g == GPB - 1) ? vn : go[g + 1];
        for (int kk = (start + 127) >> 7; (kk << 7) < end; kk++)
            lut[kk] = (unsigned short)g;
    }

    if (b == 0 && t == 0) { g_sum1 = 0.0; g_sum2 = 0.0; g_cnt1 = 0; g_cnt2 = 0; }
}

// ======== select: rank -> pixel (smem offsets/LUT, L2 bit-words) ========
__device__ __forceinline__ int rank_select(int j, const int* sgoff,
                                           const unsigned short* slut,
                                           const unsigned char* bytesBatch) {
    int g = slut[j >> 7];
    while (sgoff[g + 1] <= j) g++;
    int r = j - sgoff[g];

    const ulonglong2* bp =
        reinterpret_cast<const ulonglong2*>(bytesBatch + (size_t)g * 32);
    ulonglong2 q0 = bp[0];
    ulonglong2 q1 = bp[1];

    unsigned long long w = q0.x; int wsel = 0;
    int q = __popcll(q0.x);
    if (r >= q) { r -= q; q = __popcll(q0.y);
        if (r >= q) { r -= q; q = __popcll(q1.x);
            if (r >= q) { r -= q; w = q1.y; wsel = 3; }
            else        {         w = q1.x; wsel = 2; } }
        else        {         w = q0.y; wsel = 1; } }
    unsigned lo = (unsigned)w; int pl = __popc(lo);
    int bit = (r < pl) ? (int)__fns(lo, 0, r + 1)
                       : 32 + (int)__fns((unsigned)(w >> 32), 0, r - pl + 1);
    return g * 256 + wsel * 64 + bit;
}

// ======== kernel 3: sample gather + reduce (2 samples/thread) ========
__global__ void __launch_bounds__(256) k_sample(const float* __restrict__ d3,
                                                const float* __restrict__ dp,
                                                const int* __restrict__ s1,
                                                const int* __restrict__ s2,
                                                float* __restrict__ out) {
    const int t = threadIdx.x, lane = t & 31, wid = t >> 5;
    const int b = blockIdx.x >> 4;                       // 16 blocks per batch
    const int base = b * PSAMP + (blockIdx.x & 15) * 512;

    __shared__ __align__(16) int            sgoff[GPB + 4];  // 4 KB + pad (16B aligned)
    __shared__ __align__(16) unsigned short slut[LUTN];      // 4 KB (16B aligned)
    __shared__ float sf1[8], sf2[8];
    __shared__ int   si1[8], si2[8];

    // prologue: 8 KB L2 -> smem copy (vectorized, 16B aligned both sides)
    {
        const uint4* gsrc = reinterpret_cast<const uint4*>(g_grpOff + b * GPB);
        uint4* gdst = reinterpret_cast<uint4*>(sgoff);
        gdst[t] = gsrc[t];                               // 1024 ints
        const uint4* lsrc = reinterpret_cast<const uint4*>(g_lut + b * LUTN);
        uint4* ldst = reinterpret_cast<uint4*>(slut);
        ldst[t] = lsrc[t];                               // 2048 u16
        if (t == 0) sgoff[GPB] = g_validNum[b];
    }
    __syncthreads();

    const int vn = sgoff[GPB];
    const size_t bo = (size_t)b * HW_TOTAL;
    const unsigned char* bytesBatch = g_bytes + (size_t)b * 32768;

    // two samples per thread: base+t and base+t+256
    const int i0 = base + t;
    const int i1 = base + t + 256;
    const int j1a = s1[i0] % vn, j2a = s2[i0] % vn;
    const int j1b = s1[i1] % vn, j2b = s2[i1] % vn;

    const int p1a = rank_select(j1a, sgoff, slut, bytesBatch);
    const int p2a = rank_select(j2a, sgoff, slut, bytesBatch);
    const int p1b = rank_select(j1b, sgoff, slut, bytesBatch);
    const int p2b = rank_select(j2b, sgoff, slut, bytesBatch);

    const float a_a = d3[bo + p1a];
    const float b_a = d3[bo + p2a];
    const float a_b = d3[bo + p1b];
    const float b_b = d3[bo + p2b];
    const float df_a = dp[bo + p1a] - dp[bo + p2a];
    const float df_b = dp[bo + p1b] - dp[bo + p2b];

    float ls1 = 0.f, ls2 = 0.f;
    int lc1 = 0, lc2 = 0;
    if (a_a > b_a + EPS_F) { ls1 += fmaxf(-df_a, 0.f); lc1++; }
    if (a_a < b_a - EPS_F) { ls2 += fmaxf(df_a, 0.f);  lc2++; }
    if (a_b > b_b + EPS_F) { ls1 += fmaxf(-df_b, 0.f); lc1++; }
    if (a_b < b_b - EPS_F) { ls2 += fmaxf(df_b, 0.f);  lc2++; }

    #pragma unroll
    for (int o = 16; o; o >>= 1) {
        ls1 += __shfl_down_sync(0xFFFFFFFFu, ls1, o);
        ls2 += __shfl_down_sync(0xFFFFFFFFu, ls2, o);
        lc1 += __shfl_down_sync(0xFFFFFFFFu, lc1, o);
        lc2 += __shfl_down_sync(0xFFFFFFFFu, lc2, o);
    }
    if (lane == 0) { sf1[wid] = ls1; sf2[wid] = ls2; si1[wid] = lc1; si2[wid] = lc2; }
    __syncthreads();
    if (wid == 0) {
        float v1 = (lane < 8) ? sf1[lane] : 0.f;
        float v2 = (lane < 8) ? sf2[lane] : 0.f;
        int   i1r = (lane < 8) ? si1[lane] : 0;
        int   i2r = (lane < 8) ? si2[lane] : 0;
        #pragma unroll
        for (int o = 4; o; o >>= 1) {
            v1 += __shfl_down_sync(0xFFFFFFFFu, v1, o);
            v2 += __shfl_down_sync(0xFFFFFFFFu, v2, o);
            i1r += __shfl_down_sync(0xFFFFFFFFu, i1r, o);
            i2r += __shfl_down_sync(0xFFFFFFFFu, i2r, o);
        }
        if (lane == 0) {
            atomicAdd(&g_sum1, (double)v1);
            atomicAdd(&g_sum2, (double)v2);
            atomicAdd(&g_cnt1, i1r);
            atomicAdd(&g_cnt2, i2r);
        }
    }

    // last-block finalize
    __threadfence();
    __syncthreads();
    if (t == 0) {
        if (atomicAdd(&g_done2, 1) == SMP_BLOCKS - 1) {
            g_done2 = 0;
            double a1 = *(volatile double*)&g_sum1;
            double a2 = *(volatile double*)&g_sum2;
            int    n1 = *(volatile int*)&g_cnt1;
            int    n2 = *(volatile int*)&g_cnt2;
            out[0] = 0.5f * (float)(a1 / (double)n1 + a2 / (double)n2);
        }
    }
}

extern "C" void kernel_launch(void* const* d_in, const int* in_sizes, int n_in,
                              void* d_out, int out_size) {
    const float* d3   = (const float*)d_in[0];   // depth_3dmm
    const float* dp   = (const float*)d_in[1];   // depth_pigan
    const int*   mask = (const int*)d_in[2];
    const int*   s1   = (const int*)d_in[3];
    const int*   s2   = (const int*)d_in[4];

    k_count<<<CNT_BLOCKS, 512>>>(mask);
    k_prep<<<BATCH, 256>>>();
    k_sample<<<SMP_BLOCKS, 256>>>(d3, dp, s1, s2, (float*)d_out);
}

// round 9
// speedup vs baseline: 1.2436x; 1.0880x over previous
#include <cuda_runtime.h>
#include <cstdint>

// Problem constants (fixed by the reference)
#define HW_TOTAL (512 * 512)                  // 262144 pixels per batch image
#define BATCH 32
#define PSAMP 8192
#define NSAMP (BATCH * PSAMP)                 // 262144 samples
#define CHUNK 2048                            // pixels per logical chunk
#define CPB 128                               // chunks per batch
#define NCHUNKS (BATCH * CPB)                 // 4096
#define GPB 1024                              // 256-px groups per batch
#define LUTN 2048                             // rank->group LUT entries (gran 128)
#define EPS_F 1e-5f

#define CNT_BLOCKS 1024                       // 8192 px (4 chunks) per block
#define SMP_BLOCKS (NSAMP / 512)              // 512 (512 samples per block)

// -------- device scratch (static globals: no runtime allocation) --------
__device__ __align__(256) unsigned char g_bytes[(size_t)NCHUNKS * 256]; // 1 MB packed mask
__device__ __align__(16)  unsigned short g_subOff[NCHUNKS * 8];         // 64 KB group offsets in chunk
__device__ int      g_chunkCnt[NCHUNKS];
__device__ __align__(16) int            g_grpOff[BATCH * GPB];          // 128 KB batch-rel group offsets
__device__ __align__(16) unsigned short g_lut[BATCH * LUTN];            // 128 KB rank(128)->group
__device__ int      g_validNum[BATCH];
__device__ double   g_sum1, g_sum2;
__device__ int      g_cnt1, g_cnt2;
__device__ unsigned g_done2;                  // zero-init; self-resetting

// ======== kernel 1: mask -> bitmask + subOff + chunk counts ========
// 512 threads, 16 px/thread (4x int4), 8192 px = 4 chunks per block.
__global__ void __launch_bounds__(512) k_count(const int* __restrict__ mask) {
    const int t = threadIdx.x, lane = t & 31, wid = t >> 5;
    const size_t basePx = (size_t)blockIdx.x * 8192 + (size_t)t * 16;

    const int4* p = reinterpret_cast<const int4*>(mask + basePx);
    int4 v0 = p[0];
    int4 v1 = p[1];
    int4 v2 = p[2];
    int4 v3 = p[3];

    unsigned m16 =
          (unsigned)(v0.x != 0)       | (unsigned)(v0.y != 0) << 1
        | (unsigned)(v0.z != 0) << 2  | (unsigned)(v0.w != 0) << 3
        | (unsigned)(v1.x != 0) << 4  | (unsigned)(v1.y != 0) << 5
        | (unsigned)(v1.z != 0) << 6  | (unsigned)(v1.w != 0) << 7
        | (unsigned)(v2.x != 0) << 8  | (unsigned)(v2.y != 0) << 9
        | (unsigned)(v2.z != 0) << 10 | (unsigned)(v2.w != 0) << 11
        | (unsigned)(v3.x != 0) << 12 | (unsigned)(v3.y != 0) << 13
        | (unsigned)(v3.z != 0) << 14 | (unsigned)(v3.w != 0) << 15;

    // little-endian u16 store matches byte-granular bitmask layout
    reinterpret_cast<unsigned short*>(g_bytes)[blockIdx.x * 512 + t] =
        (unsigned short)m16;

    // half-warp (= 256-px group) reduction
    const int c = __popc(m16);
    const unsigned hm = (lane < 16) ? 0x0000FFFFu : 0xFFFF0000u;
    const int gsum = __reduce_add_sync(hm, c);

    __shared__ int gcnt[32];                  // 32 groups per block
    if ((lane & 15) == 0) gcnt[wid * 2 + (lane >> 4)] = gsum;
    __syncthreads();

    if (wid == 0) {
        int val = gcnt[lane];
        int seg = lane & 7;                    // group within chunk
        int inc = val;
        #pragma unroll
        for (int o = 1; o < 8; o <<= 1) {
            int u = __shfl_up_sync(0xFFFFFFFFu, inc, o);
            if (seg >= o) inc += u;
        }
        int chunk = blockIdx.x * 4 + (lane >> 3);
        g_subOff[chunk * 8 + seg] = (unsigned short)(inc - val);
        if (seg == 7) g_chunkCnt[chunk] = inc;
    }
}

// ======== kernel 2: per-batch scan + grpOff + LUT precompute ========
__global__ void __launch_bounds__(256) k_prep() {
    const int b = blockIdx.x;
    const int t = threadIdx.x, lane = t & 31, wid = t >> 5;

    __shared__ int scoff[CPB];
    __shared__ int svn;

    if (wid == 0) {   // scan this batch's 128 chunk counts (4 per lane)
        int base = b * CPB + lane * 4;
        int c0 = g_chunkCnt[base + 0];
        int c1 = g_chunkCnt[base + 1];
        int c2 = g_chunkCnt[base + 2];
        int c3 = g_chunkCnt[base + 3];
        int s4 = c0 + c1 + c2 + c3;
        int inc = s4;
        #pragma unroll
        for (int o = 1; o < 32; o <<= 1) {
            int v = __shfl_up_sync(0xFFFFFFFFu, inc, o);
            if (lane >= o) inc += v;
        }
        int exc = inc - s4;
        scoff[lane * 4 + 0] = exc;
        scoff[lane * 4 + 1] = exc + c0;
        scoff[lane * 4 + 2] = exc + c0 + c1;
        scoff[lane * 4 + 3] = exc + c0 + c1 + c2;
        int tot = __shfl_sync(0xFFFFFFFFu, inc, 31);
        if (lane == 0) { g_validNum[b] = tot; svn = tot; }
    }
    __syncthreads();

    // group offsets = chunkOff + subOff (4 groups per thread)
    int* go = g_grpOff + b * GPB;
    #pragma unroll
    for (int k = 0; k < 4; k++) {
        int g = t * 4 + k;
        int ch = g >> 3;
        go[g] = scoff[ch] + (int)g_subOff[(b * CPB + ch) * 8 + (g & 7)];
    }
    __syncthreads();

    // rank(128) -> group LUT
    unsigned short* lut = g_lut + b * LUTN;
    const int vn = svn;
    #pragma unroll
    for (int k = 0; k < 4; k++) {
        int g = t * 4 + k;
        int start = go[g];
        int end = (g == GPB - 1) ? vn : go[g + 1];
        for (int kk = (start + 127) >> 7; (kk << 7) < end; kk++)
            lut[kk] = (unsigned short)g;
    }

    if (b == 0 && t == 0) { g_sum1 = 0.0; g_sum2 = 0.0; g_cnt1 = 0; g_cnt2 = 0; }
}

// ======== select: rank -> pixel (smem offsets/LUT, L2 bit-words) ========
__device__ __forceinline__ int rank_select(int j, const int* sgoff,
                                           const unsigned short* slut,
                                           const unsigned char* bytesBatch) {
    int g = slut[j >> 7];
    while (sgoff[g + 1] <= j) g++;
    int r = j - sgoff[g];

    const ulonglong2* bp =
        reinterpret_cast<const ulonglong2*>(bytesBatch + (size_t)g * 32);
    ulonglong2 q0 = bp[0];
    ulonglong2 q1 = bp[1];

    unsigned long long w = q0.x; int wsel = 0;
    int q = __popcll(q0.x);
    if (r >= q) { r -= q; q = __popcll(q0.y);
        if (r >= q) { r -= q; q = __popcll(q1.x);
            if (r >= q) { r -= q; w = q1.y; wsel = 3; }
            else        {         w = q1.x; wsel = 2; } }
        else        {         w = q0.y; wsel = 1; } }
    unsigned lo = (unsigned)w; int pl = __popc(lo);
    int bit = (r < pl) ? (int)__fns(lo, 0, r + 1)
                       : 32 + (int)__fns((unsigned)(w >> 32), 0, r - pl + 1);
    return g * 256 + wsel * 64 + bit;
}

// ======== kernel 3: sample gather + reduce (1 sample/thread, 512 thr) ======
__global__ void __launch_bounds__(512) k_sample(const float* __restrict__ d3,
                                                const float* __restrict__ dp,
                                                const int* __restrict__ s1,
                                                const int* __restrict__ s2,
                                                float* __restrict__ out) {
    const int t = threadIdx.x, lane = t & 31, wid = t >> 5;
    const int b = blockIdx.x >> 4;                       // 16 blocks per batch
    const int i = b * PSAMP + (blockIdx.x & 15) * 512 + t;

    __shared__ __align__(16) int            sgoff[GPB + 4];  // 4 KB + pad
    __shared__ __align__(16) unsigned short slut[LUTN];      // 4 KB
    __shared__ float sf1[16], sf2[16];
    __shared__ int   si1[16], si2[16];

    // prologue: 8 KB L2 -> smem (one 16B op per thread)
    if (t < 256) {
        reinterpret_cast<uint4*>(sgoff)[t] =
            reinterpret_cast<const uint4*>(g_grpOff + b * GPB)[t];
    } else {
        reinterpret_cast<uint4*>(slut)[t - 256] =
            reinterpret_cast<const uint4*>(g_lut + b * LUTN)[t - 256];
    }
    if (t == 0) sgoff[GPB] = g_validNum[b];
    __syncthreads();

    const int vn = sgoff[GPB];
    const size_t bo = (size_t)b * HW_TOTAL;
    const unsigned char* bytesBatch = g_bytes + (size_t)b * 32768;

    const int j1 = s1[i] % vn;
    const int j2 = s2[i] % vn;
    const int p1 = rank_select(j1, sgoff, slut, bytesBatch);
    const int p2 = rank_select(j2, sgoff, slut, bytesBatch);

    const float av = d3[bo + p1];
    const float bv = d3[bo + p2];
    const float diff = dp[bo + p1] - dp[bo + p2];

    float ls1 = 0.f, ls2 = 0.f;
    int lc1 = 0, lc2 = 0;
    if (av > bv + EPS_F) { ls1 = fmaxf(-diff, 0.f); lc1 = 1; }
    if (av < bv - EPS_F) { ls2 = fmaxf(diff, 0.f);  lc2 = 1; }

    #pragma unroll
    for (int o = 16; o; o >>= 1) {
        ls1 += __shfl_down_sync(0xFFFFFFFFu, ls1, o);
        ls2 += __shfl_down_sync(0xFFFFFFFFu, ls2, o);
        lc1 += __shfl_down_sync(0xFFFFFFFFu, lc1, o);
        lc2 += __shfl_down_sync(0xFFFFFFFFu, lc2, o);
    }
    if (lane == 0) { sf1[wid] = ls1; sf2[wid] = ls2; si1[wid] = lc1; si2[wid] = lc2; }
    __syncthreads();
    if (wid == 0) {
        float v1 = (lane < 16) ? sf1[lane] : 0.f;
        float v2 = (lane < 16) ? sf2[lane] : 0.f;
        int   i1r = (lane < 16) ? si1[lane] : 0;
        int   i2r = (lane < 16) ? si2[lane] : 0;
        #pragma unroll
        for (int o = 8; o; o >>= 1) {
            v1 += __shfl_down_sync(0xFFFFFFFFu, v1, o);
            v2 += __shfl_down_sync(0xFFFFFFFFu, v2, o);
            i1r += __shfl_down_sync(0xFFFFFFFFu, i1r, o);
            i2r += __shfl_down_sync(0xFFFFFFFFu, i2r, o);
        }
        if (lane == 0) {
            atomicAdd(&g_sum1, (double)v1);
            atomicAdd(&g_sum2, (double)v2);
            atomicAdd(&g_cnt1, i1r);
            atomicAdd(&g_cnt2, i2r);
        }
    }

    // last-block finalize
    __threadfence();
    __syncthreads();
    if (t == 0) {
        if (atomicAdd(&g_done2, 1) == SMP_BLOCKS - 1) {
            g_done2 = 0;
            double a1 = *(volatile double*)&g_sum1;
            double a2 = *(volatile double*)&g_sum2;
            int    n1 = *(volatile int*)&g_cnt1;
            int    n2 = *(volatile int*)&g_cnt2;
            out[0] = 0.5f * (float)(a1 / (double)n1 + a2 / (double)n2);
        }
    }
}

extern "C" void kernel_launch(void* const* d_in, const int* in_sizes, int n_in,
                              void* d_out, int out_size) {
    const float* d3   = (const float*)d_in[0];   // depth_3dmm
    const float* dp   = (const float*)d_in[1];   // depth_pigan
    const int*   mask = (const int*)d_in[2];
    const int*   s1   = (const int*)d_in[3];
    const int*   s2   = (const int*)d_in[4];

    k_count<<<CNT_BLOCKS, 512>>>(mask);
    k_prep<<<BATCH, 256>>>();
    k_sample<<<SMP_BLOCKS, 512>>>(d3, dp, s1, s2, (float*)d_out);
}